// round 11
// baseline (speedup 1.0000x reference)
#include <cuda_runtime.h>
#include <cstdint>

#define NB 64       // batch
#define NSLOT 11    // 8 (L1 strips) + 2 (L2 strips) + 1 (L3)
#define NBLK (NB * NSLOT)
#define FINF __int_as_float(0x7f800000)

// Per-(image,slot) exact integer partials [y-sum, x-sum, count] and per-image
// truth-center sums. Every entry rewritten each run -> no init pass needed.
__device__ int   g_part[NB][NSLOT][3];
__device__ float g_tsum[NB][2];
__device__ int   g_ticket;   // zero at load; last block resets to 0 each run

// Raw row-segment load only: 1 LDG.128 + 2 predicated per-lane edge loads.
// NO dependent compute here -- consumption is deferred a full iteration so
// the loads stay in flight (true software pipelining).
template <int W, int CG>
__device__ __forceinline__ void load_row_raw(const float* __restrict__ h, int row,
                                             int cg, bool hl, bool hr,
                                             float (&v)[6]) {
    const float* r = h + (size_t)row * W + 4 * cg;
    float4 C = *reinterpret_cast<const float4*>(r);
    v[1] = C.x; v[2] = C.y; v[3] = C.z; v[4] = C.w;
    v[0] = hl ? r[-1] : FINF;
    v[5] = hr ? r[4]  : FINF;
}

// Sliding 3-window horizontal maxima for a loaded row.
__device__ __forceinline__ void calc_hm(const float (&v)[6], float (&hm)[4]) {
    float p0 = fmaxf(v[0], v[1]), p1 = fmaxf(v[1], v[2]);
    float p2 = fmaxf(v[2], v[3]), p3 = fmaxf(v[3], v[4]);
    hm[0] = fmaxf(p0, v[2]); hm[1] = fmaxf(p1, v[3]);
    hm[2] = fmaxf(p2, v[4]); hm[3] = fmaxf(p3, v[5]);
}

// Packed per-thread accumulator: [sy:14 | sx:14 | cnt:4].
// Safe: per thread (<=4x16 tile), strict peaks have spacing >=2 in each dim,
// so cnt <= 8*ceil(K/2)/2... bounded by 16 for K<=16; sy,sx <= 16*1016 -- use
// K<=8 tiles => cnt <= 8, sy,sx <= 8128 < 2^14. Fields never overflow.
//
// Thread computes peaks for 4 columns x K rows. Decoupled pipeline:
//   iter r: issue raw load of logical row r+3, compute hm of row r+2
//   (loaded one full iteration ago), peak-test center row r+1.
template <int H, int W, int Rm, int CG, int K>
__device__ __forceinline__ void peak_strip(const float* __restrict__ p, int n,
                                           int base_i, int cg, unsigned& packed) {
    const float* __restrict__ h = p + ((size_t)n * 3 + 2) * (size_t)(H * W);
    const bool hl = (cg > 0), hr = (cg < CG - 1);
    // per-strip base increment: (Rm*base_i)<<18 | (Rm*4*cg)<<4 | 1
    const unsigned base_inc = ((unsigned)(Rm * base_i) << 18) |
                              ((unsigned)(Rm * 4 * cg) << 4) | 1u;

    float v[3][6];
    float hm[3][4];
    load_row_raw<W, CG>(h, base_i > 0 ? base_i - 1 : 0, cg, hl, hr, v[0]);
    load_row_raw<W, CG>(h, base_i, cg, hl, hr, v[1]);
    {
        int r1 = base_i + 1; if (r1 > H - 1) r1 = H - 1;
        load_row_raw<W, CG>(h, r1, cg, hl, hr, v[2]);
    }
    calc_hm(v[0], hm[0]);
    calc_hm(v[1], hm[1]);

#pragma unroll
    for (int r = 0; r < K; r++) {
        if (r <= K - 2) {   // issue load of logical row r+3 (global i+2)
            int nr = base_i + r + 2; if (nr > H - 1) nr = H - 1;
            load_row_raw<W, CG>(h, nr, cg, hl, hr, v[r % 3]);
        }
        const int mid = (r + 1) % 3, bot = (r + 2) % 3, top = r % 3;
        calc_hm(v[bot], hm[bot]);   // row loaded one full iteration ago
        int i = base_i + r;
        bool rv = (i >= 1) && (i <= H - 2);
        // compile-time per-iteration offset: (Rm*r)<<18 (+ (Rm*k)<<4 per col)
#pragma unroll
        for (int k = 0; k < 4; k++) {
            float mx = fmaxf(fmaxf(hm[top][k], hm[bot][k]),
                             fmaxf(v[mid][k], v[mid][k + 2]));
            if (rv && (v[mid][k + 1] > mx))
                packed += base_inc + (((unsigned)(Rm * r) << 18) |
                                      ((unsigned)(Rm * k) << 4));
        }
    }
}

__device__ __forceinline__ float warp_sum_f(float v) {
#pragma unroll
    for (int o = 16; o; o >>= 1) v += __shfl_xor_sync(0xffffffffu, v, o);
    return v;
}

__global__ void __launch_bounds__(256, 5)
fused_kernel(const float* __restrict__ p1,
             const float* __restrict__ p2,
             const float* __restrict__ p3,
             const float* __restrict__ target,
             float* __restrict__ out) {
    int n = blockIdx.y;
    int slot = blockIdx.x;
    int tid = threadIdx.x;
    unsigned packed = 0;

    // slot-10 blocks (lightest work) also compute the truth-center sums for
    // their image; loads issued first so they overlap the peak loads.
    if (slot == 10 && tid < 32) {
        const float* t = target + (size_t)n * 32 * 5 + (size_t)tid * 5;
        float v0 = 0.5f * (t[2] + t[0]);
        float v1 = 0.5f * (t[3] + t[1]);
        v0 = warp_sum_f(v0);
        v1 = warp_sum_f(v1);
        if (tid == 0) { g_tsum[n][0] = v0; g_tsum[n][1] = v1; }
    }

    if (slot < 8) {
        // 256x256: 64 col-groups x 4 row-teams; strip = 32 rows, team = 8 rows
        int cg = tid & 63, rt = tid >> 6;
        peak_strip<256, 256, 4, 64, 8>(p1, n, slot * 32 + rt * 8, cg, packed);
    } else if (slot < 10) {
        // 128x128: 32 col-groups x 8 row-teams; strip = 64 rows, team = 8 rows
        int cg = tid & 31, rt = tid >> 5;
        peak_strip<128, 128, 8, 32, 8>(p2, n, (slot - 8) * 64 + rt * 8, cg, packed);
    } else {
        // 64x64: 16 col-groups x 16 row-teams; team = 4 rows (covers 64 rows)
        int cg = tid & 15, rt = tid >> 4;
        peak_strip<64, 64, 16, 16, 4>(p3, n, rt * 4, cg, packed);
    }

    // unpack per-thread (fields too small for cross-thread sums), then reduce
    int cnt = (int)(packed & 15u);
    int sx  = (int)((packed >> 4) & 16383u);
    int sy  = (int)(packed >> 18);

    sy  = __reduce_add_sync(0xffffffffu, sy);
    sx  = __reduce_add_sync(0xffffffffu, sx);
    cnt = __reduce_add_sync(0xffffffffu, cnt);

    __shared__ int s[3][8];
    __shared__ bool is_last;
    int w = tid >> 5, lane = tid & 31;
    if (lane == 0) { s[0][w] = sy; s[1][w] = sx; s[2][w] = cnt; }
    __syncthreads();
    if (tid == 0) {
        int ty = 0, tx = 0, tc = 0;
#pragma unroll
        for (int k = 0; k < 8; k++) { ty += s[0][k]; tx += s[1][k]; tc += s[2][k]; }
        g_part[n][slot][0] = ty;
        g_part[n][slot][1] = tx;
        g_part[n][slot][2] = tc;
        __threadfence();
        int t = atomicAdd(&g_ticket, 1);
        is_last = (t == NBLK - 1);
    }
    __syncthreads();
    if (!is_last) return;

    // ---- epilogue: the elected last block does the loss ----
    if (tid == 0) g_ticket = 0;   // reset for the next graph replay

    __shared__ float r_offx[2], r_offy[2], r_c0[2], r_c1[2], r_t0[2], r_t1[2];
    __shared__ int r_pc[2];

    if (tid < NB) {
        int cyi = 0, cxi = 0, ci = 0;
#pragma unroll
        for (int sl = 0; sl < NSLOT; sl++) {
            cyi += __ldcg(&g_part[tid][sl][0]);
            cxi += __ldcg(&g_part[tid][sl][1]);
            ci  += __ldcg(&g_part[tid][sl][2]);
        }
        float ts0 = __ldcg(&g_tsum[tid][0]);
        float ts1 = __ldcg(&g_tsum[tid][1]);
        float cy = (float)cyi, cx = (float)cxi;
        float dy = fabsf(cy - ts0);
        float dx = fabsf(cx - ts1);
        float sly = (dy < 1.f) ? 0.5f * dy * dy : dy - 0.5f;
        float slx = (dx < 1.f) ? 0.5f * dx * dx : dx - 0.5f;

        float offx = warp_sum_f(sly);
        float offy = warp_sum_f(slx);
        float c0   = warp_sum_f(cy);
        float c1   = warp_sum_f(cx);
        float t0   = warp_sum_f(ts0);
        float t1   = warp_sum_f(ts1);
        int pc = ci;
#pragma unroll
        for (int o = 16; o; o >>= 1) pc += __shfl_xor_sync(0xffffffffu, pc, o);

        if (lane == 0) {
            r_offx[w] = offx; r_offy[w] = offy;
            r_c0[w] = c0; r_c1[w] = c1; r_t0[w] = t0; r_t1[w] = t1;
            r_pc[w] = pc;
        }
    }
    __syncthreads();
    if (tid == 0) {
        float offx = r_offx[0] + r_offx[1];
        float offy = r_offy[0] + r_offy[1];
        float cst0 = r_c0[0] + r_c0[1];
        float cst1 = r_c1[0] + r_c1[1];
        float tst0 = r_t0[0] + r_t0[1];
        float tst1 = r_t1[0] + r_t1[1];
        int pc = r_pc[0] + r_pc[1];
        float sgx = offx / fabsf(offx);
        float sgy = offy / fabsf(offy);
        out[0] = (sgx * (cst0 - tst0) + sgy * (cst1 - tst1)) / (float)pc;
    }
}

extern "C" void kernel_launch(void* const* d_in, const int* in_sizes, int n_in,
                              void* d_out, int out_size) {
    const float* p1  = (const float*)d_in[0];
    const float* p2  = (const float*)d_in[1];
    const float* p3  = (const float*)d_in[2];
    const float* tgt = (const float*)d_in[3];
    float* out = (float*)d_out;

    dim3 grid(NSLOT, NB);
    fused_kernel<<<grid, 256>>>(p1, p2, p3, tgt, out);
}